// round 7
// baseline (speedup 1.0000x reference)
#include <cuda_runtime.h>
#include <cstdint>

// Problem constants
#define BB   4096
#define TT   2048
#define HH   128
#define BR   32            // batch rows per CTA
#define NCTA (BB / BR)     // 128 CTAs
#define NTHR 256           // 8 warps -> 2 per SMSP
#define NOUT 8
#define KSTR 68            // smem row stride (floats): 32 duplicated pairs + pad, 16B-aligned

typedef unsigned long long ull;

// ---------- packed fp32x2 helpers ----------
__device__ __forceinline__ ull pack2(float a, float b) {
    ull r; asm("mov.b64 %0,{%1,%2};" : "=l"(r) : "f"(a), "f"(b)); return r;
}
__device__ __forceinline__ void unpack2(ull p, float& a, float& b) {
    asm("mov.b64 {%0,%1},%2;" : "=f"(a), "=f"(b) : "l"(p));
}
__device__ __forceinline__ ull fma2(ull a, ull b, ull c) {
    ull d; asm("fma.rn.f32x2 %0,%1,%2,%3;" : "=l"(d) : "l"(a), "l"(b), "l"(c)); return d;
}

__device__ __forceinline__ float sigf(float x) {
    return __fdividef(1.0f, 1.0f + __expf(-x));
}
__device__ __forceinline__ float tanhfast(float x) {
    return fmaf(2.0f, sigf(2.0f * x), -1.0f);
}

// Transposed weights: [mat][k*128 + j] = float4 (g0,g1,g2,g3) for unit j, col k.
// Loaded as ulonglong2: .x = (g0,g1), .y = (g2,g3) — native FFMA2 operands, no MOVs.
// Lanes j..j+31 are 16B-contiguous -> 4 lines per LDG.128 (coalesced).
__device__ float4 g_wt[3][HH * HH];

__global__ void prep_w_kernel(const float* __restrict__ whh1,
                              const float* __restrict__ wih2,
                              const float* __restrict__ whh2)
{
    const int idx = blockIdx.x * blockDim.x + threadIdx.x;   // 0..16383
    if (idx >= HH * HH) return;
    const int k = idx >> 7, j = idx & 127;
    const float* Ws[3] = { whh1, wih2, whh2 };
    #pragma unroll
    for (int m = 0; m < 3; ++m) {
        const float* W = Ws[m];
        g_wt[m][idx] = make_float4(W[(0 * HH + j) * HH + k],
                                   W[(1 * HH + j) * HH + k],
                                   W[(2 * HH + j) * HH + k],
                                   W[(3 * HH + j) * HH + k]);
    }
}

// 16x512x128 fp32 GEMM-accumulate slice (this thread's 16 rows, unit j, 4 gates):
//   acc[0][r] = packed (gate0, gate1) acc for row r;  acc[1][r] = (gate2, gate3).
//   acc[p][r] (+)= (w_pair) * (h[k][r], h[k][r])   over k = 0..127
// h stored DUPLICATED in smem: LDS.128 yields (h_r,h_r,h_r+1,h_r+1) -> two native
// duplicated operands. Weights: 1 coalesced LDG.128/k, prefetched 4-k ahead.
// Inner loop is pure LDG/LDS/FFMA2 — zero MOV packing.
__device__ __forceinline__ void gemm_acc(ull (&acc)[2][16],
                                         const ulonglong2* __restrict__ wt,  // g_wt[m] + j
                                         const float* __restrict__ hbuf)     // h + 2*rbase
{
    ulonglong2 w[4];
    #pragma unroll
    for (int i = 0; i < 4; ++i) w[i] = __ldg(wt + i * HH);
    #pragma unroll 1
    for (int k4 = 0; k4 < 32; ++k4) {
        ulonglong2 wn[4];
        const int kb = (k4 < 31) ? (k4 + 1) * 4 : 124;    // prefetch next 4 k
        #pragma unroll
        for (int i = 0; i < 4; ++i) wn[i] = __ldg(wt + (kb + i) * HH);
        const float* hk = hbuf + (k4 * 4) * KSTR;
        #pragma unroll
        for (int kk = 0; kk < 4; ++kk) {
            const float* hkk = hk + kk * KSTR;
            #pragma unroll
            for (int rq = 0; rq < 8; ++rq) {               // 2 duplicated rows per LDS.128
                const ulonglong2 hv = *(const ulonglong2*)(hkk + 4 * rq);
                const int r = 2 * rq;
                acc[0][r]   = fma2(w[kk].x, hv.x, acc[0][r]);
                acc[1][r]   = fma2(w[kk].y, hv.x, acc[1][r]);
                acc[0][r+1] = fma2(w[kk].x, hv.y, acc[0][r+1]);
                acc[1][r+1] = fma2(w[kk].y, hv.y, acc[1][r+1]);
            }
        }
        #pragma unroll
        for (int i = 0; i < 4; ++i) w[i] = wn[i];
    }
}

// Dynamic smem layout (floats); h/x stored duplicated: row k base = k*KSTR, row r at +2r
#define SM_H1 0                          // [2][128][KSTR]
#define SM_H2 (SM_H1 + 2 * HH * KSTR)    // [2][128][KSTR]
#define SM_XS (SM_H2 + 2 * HH * KSTR)    // [64][KSTR]  x-tile, duplicated
#define SM_W1 (SM_XS + 64 * KSTR)        // [128][8]  (transposed [k][oo])
#define SM_W2 (SM_W1 + NOUT * HH)        // [128][8]
#define SM_B1 (SM_W2 + NOUT * HH)        // [8]
#define SM_B2 (SM_B1 + NOUT)             // [8]
#define SM_TOT (SM_B2 + NOUT)            // ~41232 floats ~= 161 KB

__global__ void __launch_bounds__(NTHR, 1)
lstm_kernel(const float* __restrict__ x,
            const float* __restrict__ wih1,
            const float* __restrict__ bih1, const float* __restrict__ bhh1,
            const float* __restrict__ bih2, const float* __restrict__ bhh2,
            const float* __restrict__ W1, const float* __restrict__ b1,
            const float* __restrict__ W2, const float* __restrict__ b2,
            float* __restrict__ out)
{
    extern __shared__ float sm[];
    float* h1s = sm + SM_H1;
    float* h2s = sm + SM_H2;
    float* xs  = sm + SM_XS;
    float* W1s = sm + SM_W1;
    float* W2s = sm + SM_W2;
    float* b1s = sm + SM_B1;
    float* b2s = sm + SM_B2;

    const int tid = threadIdx.x;
    const int j   = tid & 127;           // hidden unit owned by this thread
    const int rh  = tid >> 7;            // row half: rows [rh*16, rh*16+16)
    const int r0  = blockIdx.x * BR;     // first batch row of this CTA

    // ---- init smem ----
    for (int i = tid; i < 2 * HH * KSTR; i += NTHR) { h1s[i] = 0.0f; h2s[i] = 0.0f; }
    for (int i = tid; i < NOUT * HH;     i += NTHR) {
        const int oo = i / HH, k = i % HH;
        W1s[k * NOUT + oo] = W1[i];
        W2s[k * NOUT + oo] = W2[i];
    }
    if (tid < NOUT) { b1s[tid] = b1[tid]; b2s[tid] = b2[tid]; }

    // ---- per-thread constants: gate-pair packed biases + input weights ----
    float bb1[4], bb2[4], wi1[4];
    #pragma unroll
    for (int g = 0; g < 4; ++g) {
        const int row = g * HH + j;
        bb1[g] = bih1[row] + bhh1[row];
        bb2[g] = bih2[row] + bhh2[row];
        wi1[g] = wih1[row];              // W_ih1 is (512,1)
    }
    const ull b1_01 = pack2(bb1[0], bb1[1]), b1_23 = pack2(bb1[2], bb1[3]);
    const ull b2_01 = pack2(bb2[0], bb2[1]), b2_23 = pack2(bb2[2], bb2[3]);
    const ull wi_01 = pack2(wi1[0], wi1[1]), wi_23 = pack2(wi1[2], wi1[3]);

    // cell state in registers: c[cell][local row 0..15] for unit j
    float c1r[16], c2r[16];
    #pragma unroll
    for (int i = 0; i < 16; ++i) { c1r[i] = 0.0f; c2r[i] = 0.0f; }

    const ulonglong2* wt1 = (const ulonglong2*)g_wt[0] + j;   // whh1
    const ulonglong2* wt2 = (const ulonglong2*)g_wt[1] + j;   // wih2
    const ulonglong2* wt3 = (const ulonglong2*)g_wt[2] + j;   // whh2

    __syncthreads();

    ull acc[2][16];
    const int rbase   = rh * 16;
    const int rr_out  = tid >> 3;
    const int oo_out  = tid & 7;
    const size_t OUTS_BASE = (size_t)BB * NOUT;

    #pragma unroll 1
    for (int t = 0; t < TT; ++t) {
        const int cur = t & 1, nxt = cur ^ 1;
        float* h1c = h1s + cur * (HH * KSTR);
        float* h1n = h1s + nxt * (HH * KSTR);
        float* h2c = h2s + cur * (HH * KSTR);
        float* h2n = h2s + nxt * (HH * KSTR);

        // ---- stage 64 steps of x, duplicated [(x,x)] at [t][row] ----
        if ((t & 63) == 0) {
            __syncthreads();
            for (int idx = tid; idx < BR * 64; idx += NTHR) {
                const int rr = idx >> 6, tt2 = idx & 63;
                const float v = x[(size_t)(r0 + rr) * TT + t + tt2];
                *(float2*)(xs + tt2 * KSTR + 2 * rr) = make_float2(v, v);
            }
            __syncthreads();
        }
        const float* xrow = xs + (t & 63) * KSTR + 2 * rbase;

        // ---------------- cell 1 ----------------
        #pragma unroll
        for (int rq = 0; rq < 8; ++rq) {
            const ulonglong2 xv = *(const ulonglong2*)(xrow + 4 * rq);
            const int r = 2 * rq;
            acc[0][r]   = fma2(wi_01, xv.x, b1_01);
            acc[1][r]   = fma2(wi_23, xv.x, b1_23);
            acc[0][r+1] = fma2(wi_01, xv.y, b1_01);
            acc[1][r+1] = fma2(wi_23, xv.y, b1_23);
        }
        gemm_acc(acc, wt1, h1c + 2 * rbase);

        {
            float* hdst = h1n + j * KSTR + 2 * rbase;
            #pragma unroll
            for (int rq = 0; rq < 8; ++rq) {
                float i0, f0, g0, o0, i1, f1, g1, o1;
                unpack2(acc[0][2*rq],   i0, f0);
                unpack2(acc[1][2*rq],   g0, o0);
                unpack2(acc[0][2*rq+1], i1, f1);
                unpack2(acc[1][2*rq+1], g1, o1);
                const float cn0 = sigf(f0) * c1r[2*rq]   + sigf(i0) * tanhfast(g0);
                const float cn1 = sigf(f1) * c1r[2*rq+1] + sigf(i1) * tanhfast(g1);
                c1r[2*rq] = cn0; c1r[2*rq+1] = cn1;
                const float h0 = sigf(o0) * tanhfast(cn0);
                const float h1 = sigf(o1) * tanhfast(cn1);
                *(float4*)(hdst + 4 * rq) = make_float4(h0, h0, h1, h1);
            }
        }
        __syncthreads();

        // ---------------- cell 2 ----------------
        #pragma unroll
        for (int r = 0; r < 16; ++r) { acc[0][r] = b2_01; acc[1][r] = b2_23; }
        gemm_acc(acc, wt2, h1n + 2 * rbase);
        gemm_acc(acc, wt3, h2c + 2 * rbase);

        {
            float* hdst = h2n + j * KSTR + 2 * rbase;
            #pragma unroll
            for (int rq = 0; rq < 8; ++rq) {
                float i0, f0, g0, o0, i1, f1, g1, o1;
                unpack2(acc[0][2*rq],   i0, f0);
                unpack2(acc[1][2*rq],   g0, o0);
                unpack2(acc[0][2*rq+1], i1, f1);
                unpack2(acc[1][2*rq+1], g1, o1);
                const float cn0 = sigf(f0) * c2r[2*rq]   + sigf(i0) * tanhfast(g0);
                const float cn1 = sigf(f1) * c2r[2*rq+1] + sigf(i1) * tanhfast(g1);
                c2r[2*rq] = cn0; c2r[2*rq+1] = cn1;
                const float h0 = sigf(o0) * tanhfast(cn0);
                const float h1 = sigf(o1) * tanhfast(cn1);
                *(float4*)(hdst + 4 * rq) = make_float4(h0, h0, h1, h1);
            }
        }
        __syncthreads();

        // ------- out projection: out_mask = h2 @ W1^T + b1 (one dot per thread) -------
        {
            float a0 = b1s[oo_out];
            const float* wr = W1s + oo_out;
            const float* hp = h2n + 2 * rr_out;
            #pragma unroll 8
            for (int k = 0; k < HH; ++k) {
                a0 = fmaf(hp[k * KSTR], wr[k * NOUT], a0);
            }
            out[OUTS_BASE + ((size_t)(r0 + rr_out) * TT + t) * NOUT + oo_out] = a0;
        }
    }

    // ---------------- final: output_cyto = h2_final @ W2^T + b2 ----------------
    // TT even -> final h2 lives in buffer 0
    {
        const float* hp = h2s + 2 * rr_out;
        float a0 = b2s[oo_out];
        const float* wr = W2s + oo_out;
        #pragma unroll 8
        for (int k = 0; k < HH; ++k) {
            a0 = fmaf(hp[k * KSTR], wr[k * NOUT], a0);
        }
        out[(size_t)(r0 + rr_out) * NOUT + oo_out] = a0;
    }
}

extern "C" void kernel_launch(void* const* d_in, const int* in_sizes, int n_in,
                              void* d_out, int out_size)
{
    (void)n_in; (void)out_size;
    const int o = (n_in >= 2 && in_sizes[1] == 1) ? 2 : 1;

    const float* x    = (const float*)d_in[0];
    const float* wih1 = (const float*)d_in[o + 0];
    const float* whh1 = (const float*)d_in[o + 1];
    const float* bih1 = (const float*)d_in[o + 2];
    const float* bhh1 = (const float*)d_in[o + 3];
    const float* wih2 = (const float*)d_in[o + 4];
    const float* whh2 = (const float*)d_in[o + 5];
    const float* bih2 = (const float*)d_in[o + 6];
    const float* bhh2 = (const float*)d_in[o + 7];
    const float* W1   = (const float*)d_in[o + 8];
    const float* b1   = (const float*)d_in[o + 9];
    const float* W2   = (const float*)d_in[o + 10];
    const float* b2   = (const float*)d_in[o + 11];

    // 1) transpose weights into __device__ scratch (k-major, gates packed)
    prep_w_kernel<<<(HH * HH + 255) / 256, 256>>>(whh1, wih2, whh2);

    // 2) main persistent recurrence kernel
    const size_t smem = (size_t)SM_TOT * sizeof(float);   // ~161 KB
    cudaFuncSetAttribute(lstm_kernel,
                         cudaFuncAttributeMaxDynamicSharedMemorySize, (int)smem);
    lstm_kernel<<<NCTA, NTHR, smem>>>(x, wih1, bih1, bhh1, bih2, bhh2,
                                      W1, b1, W2, b2, (float*)d_out);
}

// round 8
// speedup vs baseline: 1.3393x; 1.3393x over previous
#include <cuda_runtime.h>
#include <cstdint>

// Problem constants
#define BB   4096
#define TT   2048
#define HH   128
#define BR   32            // batch rows per CTA
#define NCTA (BB / BR)     // 128 CTAs
#define NTHR 256           // 8 warps -> 2 per SMSP
#define NOUT 8
#define HSTR 36            // smem row stride (floats): 144B, 16B-aligned (LDS.128-safe)

typedef unsigned long long ull;

// ---------- packed fp32x2 helpers ----------
__device__ __forceinline__ ull pack2(float a, float b) {
    ull r; asm("mov.b64 %0,{%1,%2};" : "=l"(r) : "f"(a), "f"(b)); return r;
}
__device__ __forceinline__ void unpack2(ull p, float& a, float& b) {
    asm("mov.b64 {%0,%1},%2;" : "=f"(a), "=f"(b) : "l"(p));
}
__device__ __forceinline__ ull fma2(ull a, ull b, ull c) {
    ull d; asm("fma.rn.f32x2 %0,%1,%2,%3;" : "=l"(d) : "l"(a), "l"(b), "l"(c)); return d;
}

__device__ __forceinline__ float sigf(float x) {
    return __fdividef(1.0f, 1.0f + __expf(-x));
}
__device__ __forceinline__ float tanhfast(float x) {
    return fmaf(2.0f, sigf(2.0f * x), -1.0f);
}

// Transposed weights: [mat][k*128 + j] = float4 (g0,g1,g2,g3) for unit j, col k.
// Lanes j..j+31 are 16B-contiguous -> 4 lines per LDG.128 (coalesced).
__device__ float4 g_wt[3][HH * HH];

__global__ void prep_w_kernel(const float* __restrict__ whh1,
                              const float* __restrict__ wih2,
                              const float* __restrict__ whh2)
{
    const int idx = blockIdx.x * blockDim.x + threadIdx.x;   // 0..16383
    if (idx >= HH * HH) return;
    const int k = idx >> 7, j = idx & 127;
    const float* Ws[3] = { whh1, wih2, whh2 };
    #pragma unroll
    for (int m = 0; m < 3; ++m) {
        const float* W = Ws[m];
        g_wt[m][idx] = make_float4(W[(0 * HH + j) * HH + k],
                                   W[(1 * HH + j) * HH + k],
                                   W[(2 * HH + j) * HH + k],
                                   W[(3 * HH + j) * HH + k]);
    }
}

// One k4-group (4 k values) of the 16x512x128 GEMM slice; weight prefetch carried in wv.
__device__ __forceinline__ void gemm_k4(ull (&acc)[4][8],
                                        const float4* __restrict__ wt,    // g_wt[m] + j
                                        const float* __restrict__ hbuf,   // h + rbase
                                        int k4, float4 (&wv)[4])
{
    float4 wn[4];
    const int kb = (k4 < 31) ? (k4 + 1) * 4 : 124;      // prefetch next 4 k
    #pragma unroll
    for (int i = 0; i < 4; ++i) wn[i] = __ldg(wt + (kb + i) * HH);
    const float* hk = hbuf + (k4 * 4) * HSTR;
    #pragma unroll
    for (int kk = 0; kk < 4; ++kk) {
        const ull wp0 = pack2(wv[kk].x, wv[kk].x);
        const ull wp1 = pack2(wv[kk].y, wv[kk].y);
        const ull wp2 = pack2(wv[kk].z, wv[kk].z);
        const ull wp3 = pack2(wv[kk].w, wv[kk].w);
        const float* hkk = hk + kk * HSTR;
        #pragma unroll
        for (int rq = 0; rq < 4; ++rq) {                 // quad of rows: LDS.128
            const float4 h4 = *(const float4*)(hkk + 4 * rq);
            const ull hp0 = pack2(h4.x, h4.y);
            const ull hp1 = pack2(h4.z, h4.w);
            const int rp = 2 * rq;
            acc[0][rp]   = fma2(wp0, hp0, acc[0][rp]);
            acc[1][rp]   = fma2(wp1, hp0, acc[1][rp]);
            acc[2][rp]   = fma2(wp2, hp0, acc[2][rp]);
            acc[3][rp]   = fma2(wp3, hp0, acc[3][rp]);
            acc[0][rp+1] = fma2(wp0, hp1, acc[0][rp+1]);
            acc[1][rp+1] = fma2(wp1, hp1, acc[1][rp+1]);
            acc[2][rp+1] = fma2(wp2, hp1, acc[2][rp+1]);
            acc[3][rp+1] = fma2(wp3, hp1, acc[3][rp+1]);
        }
    }
    #pragma unroll
    for (int i = 0; i < 4; ++i) wv[i] = wn[i];
}

// One row-pair of activations (gates -> c,h), static pair index P (regs).
#define ACT_PAIR(accX, cX, hdst, P) do {                                     \
    float iv0, iv1, fv0, fv1, gv0, gv1, ov0, ov1;                            \
    unpack2(accX[0][P], iv0, iv1);                                           \
    unpack2(accX[1][P], fv0, fv1);                                           \
    unpack2(accX[2][P], gv0, gv1);                                           \
    unpack2(accX[3][P], ov0, ov1);                                           \
    {   const float cn = sigf(fv0) * cX[2*(P)] + sigf(iv0) * tanhfast(gv0);  \
        cX[2*(P)] = cn;                                                      \
        (hdst)[2*(P)] = sigf(ov0) * tanhfast(cn); }                          \
    {   const float cn = sigf(fv1) * cX[2*(P)+1] + sigf(iv1) * tanhfast(gv1);\
        cX[2*(P)+1] = cn;                                                    \
        (hdst)[2*(P)+1] = sigf(ov1) * tanhfast(cn); }                        \
} while (0)

// Dynamic smem layout (floats)
#define SM_H1  0                          // [2][128][HSTR]
#define SM_H2  (SM_H1 + 2 * HH * HSTR)    // [2][128][HSTR]
#define SM_XS  (SM_H2 + 2 * HH * HSTR)    // [64][HSTR]
#define SM_W1  (SM_XS + 64 * HSTR)        // [128][8] transposed [k][oo]
#define SM_W2  (SM_W1 + NOUT * HH)        // [128][8]
#define SM_B1  (SM_W2 + NOUT * HH)        // [8]
#define SM_B2  (SM_B1 + NOUT)             // [8]
#define SM_SB1 (SM_B2 + NOUT)             // [128][8] packed (bb1,bb1) per gate, per j
#define SM_SB2 (SM_SB1 + HH * 8)          // [128][8] packed (bb2,bb2)
#define SM_SWI (SM_SB2 + HH * 8)          // [128][8] packed (wi,wi)
#define SM_TOT (SM_SWI + HH * 8)          // ~103.6 KB

__global__ void __launch_bounds__(NTHR, 1)
lstm_kernel(const float* __restrict__ x,
            const float* __restrict__ wih1,
            const float* __restrict__ bih1, const float* __restrict__ bhh1,
            const float* __restrict__ bih2, const float* __restrict__ bhh2,
            const float* __restrict__ W1, const float* __restrict__ b1,
            const float* __restrict__ W2, const float* __restrict__ b2,
            float* __restrict__ out)
{
    extern __shared__ float sm[];
    float* h1s = sm + SM_H1;
    float* h2s = sm + SM_H2;
    float* xs  = sm + SM_XS;
    float* W1s = sm + SM_W1;
    float* W2s = sm + SM_W2;
    float* b1s = sm + SM_B1;
    float* b2s = sm + SM_B2;
    float* sb1 = sm + SM_SB1;
    float* sb2 = sm + SM_SB2;
    float* swi = sm + SM_SWI;

    const int tid = threadIdx.x;
    const int j   = tid & 127;           // hidden unit owned by this thread
    const int rh  = tid >> 7;            // row half: rows [rh*16, rh*16+16)
    const int r0  = blockIdx.x * BR;     // first batch row of this CTA

    // ---- init smem ----
    for (int i = tid; i < 2 * HH * HSTR; i += NTHR) { h1s[i] = 0.0f; h2s[i] = 0.0f; }
    for (int i = tid; i < NOUT * HH;     i += NTHR) {
        const int oo = i / HH, k = i % HH;
        W1s[k * NOUT + oo] = W1[i];
        W2s[k * NOUT + oo] = W2[i];
    }
    if (tid < NOUT) { b1s[tid] = b1[tid]; b2s[tid] = b2[tid]; }
    if (tid < HH) {
        #pragma unroll
        for (int g = 0; g < 4; ++g) {
            const int row = g * HH + tid;
            const float bb1 = bih1[row] + bhh1[row];
            const float bb2 = bih2[row] + bhh2[row];
            const float wv  = wih1[row];           // W_ih1 is (512,1)
            sb1[tid * 8 + 2 * g] = bb1; sb1[tid * 8 + 2 * g + 1] = bb1;
            sb2[tid * 8 + 2 * g] = bb2; sb2[tid * 8 + 2 * g + 1] = bb2;
            swi[tid * 8 + 2 * g] = wv;  swi[tid * 8 + 2 * g + 1] = wv;
        }
    }
    // ---- stage x tile 0 ----
    for (int idx = tid; idx < BR * 64; idx += NTHR) {
        const int rr = idx >> 6, tt2 = idx & 63;
        xs[tt2 * HSTR + rr] = x[(size_t)(r0 + rr) * TT + tt2];
    }

    // cell state in registers
    float c1r[16], c2r[16];
    #pragma unroll
    for (int i = 0; i < 16; ++i) { c1r[i] = 0.0f; c2r[i] = 0.0f; }

    const float4* wt1 = g_wt[0] + j;   // whh1
    const float4* wt2 = g_wt[1] + j;   // wih2
    const float4* wt3 = g_wt[2] + j;   // whh2
    const ull* b1pj = (const ull*)(sb1 + j * 8);
    const ull* b2pj = (const ull*)(sb2 + j * 8);
    const ull* wipj = (const ull*)(swi + j * 8);

    __syncthreads();

    ull acc1[4][8], acc2[4][8];
    const int rbase  = rh * 16;
    const int rr_out = tid >> 3;
    const int oo_out = tid & 7;
    const size_t OUTS_BASE = (size_t)BB * NOUT;

    // ---- prologue: acc1 = preacts(step 0) = b1 + wi*x(0)  (h1(-1)=0) ----
    {
        const float* xrow = xs + rbase;
        #pragma unroll
        for (int rq = 0; rq < 4; ++rq) {
            const ulonglong2 xv = *(const ulonglong2*)(xrow + 4 * rq);
            const int rp = 2 * rq;
            #pragma unroll
            for (int g = 0; g < 4; ++g) {
                acc1[g][rp]   = fma2(wipj[g], xv.x, b1pj[g]);
                acc1[g][rp+1] = fma2(wipj[g], xv.y, b1pj[g]);
            }
        }
    }

    #pragma unroll 1
    for (int t = 0; t < TT; ++t) {
        const int cur = t & 1, nxt = cur ^ 1;
        float* h1n = h1s + nxt * (HH * HSTR);
        float* h2c = h2s + cur * (HH * HSTR);
        float* h2n = h2s + nxt * (HH * HSTR);
        const float* hb1 = h1n + rbase;
        const float* hb2 = h2c + rbase;

        // ======== P1: gemm whh2*h2(t-1) into acc2, fused with act1 + proj(t-1) ========
        #pragma unroll
        for (int rp = 0; rp < 8; ++rp) {
            acc2[0][rp] = b2pj[0]; acc2[1][rp] = b2pj[1];
            acc2[2][rp] = b2pj[2]; acc2[3][rp] = b2pj[3];
        }
        {
            float4 wv[4];
            #pragma unroll
            for (int i = 0; i < 4; ++i) wv[i] = __ldg(wt3 + i * HH);
            float* h1dst = h1n + j * HSTR + rbase;
            #pragma unroll
            for (int k4 = 0; k4 < 8; ++k4) {        // fused: one act pair per group
                gemm_k4(acc2, wt3, hb2, k4, wv);
                ACT_PAIR(acc1, c1r, h1dst, k4);
            }
            float a0 = b1s[oo_out];
            #pragma unroll 1
            for (int k4 = 8; k4 < 32; ++k4) {       // fused: proj chunks of 8 k
                gemm_k4(acc2, wt3, hb2, k4, wv);
                if (k4 < 24) {
                    const int kk0 = (k4 - 8) * 8;
                    #pragma unroll
                    for (int q = 0; q < 8; ++q)
                        a0 = fmaf(h2c[(kk0 + q) * HSTR + rr_out],
                                  W1s[(kk0 + q) * NOUT + oo_out], a0);
                }
            }
            if (t)
                out[OUTS_BASE + ((size_t)(r0 + rr_out) * TT + (t - 1)) * NOUT + oo_out] = a0;
        }
        __syncthreads();   // bar1: h1(t) visible

        // ======== P2: gemm wih2*h1(t) into acc2 ========
        {
            float4 wv[4];
            #pragma unroll
            for (int i = 0; i < 4; ++i) wv[i] = __ldg(wt2 + i * HH);
            #pragma unroll 1
            for (int k4 = 0; k4 < 32; ++k4)
                gemm_k4(acc2, wt2, hb1, k4, wv);
        }

        // ---- stage next x tile when needed (P3 reads x(t+1)) ----
        if (((t + 1) & 63) == 0 && (t + 1) < TT) {
            for (int idx = tid; idx < BR * 64; idx += NTHR) {
                const int rr = idx >> 6, tt2 = idx & 63;
                xs[tt2 * HSTR + rr] = x[(size_t)(r0 + rr) * TT + (t + 1) + tt2];
            }
            __syncthreads();
        }

        // ======== P3: gemm whh1*h1(t) (+x(t+1)) into acc1, fused with act2 ========
        {
            const float* xrow = xs + ((t + 1) & 63) * HSTR + rbase;
            #pragma unroll
            for (int rq = 0; rq < 4; ++rq) {
                const ulonglong2 xv = *(const ulonglong2*)(xrow + 4 * rq);
                const int rp = 2 * rq;
                #pragma unroll
                for (int g = 0; g < 4; ++g) {
                    acc1[g][rp]   = fma2(wipj[g], xv.x, b1pj[g]);
                    acc1[g][rp+1] = fma2(wipj[g], xv.y, b1pj[g]);
                }
            }
            float4 wv[4];
            #pragma unroll
            for (int i = 0; i < 4; ++i) wv[i] = __ldg(wt1 + i * HH);
            float* h2dst = h2n + j * HSTR + rbase;
            #pragma unroll
            for (int k4 = 0; k4 < 8; ++k4) {        // fused: one act pair per group
                gemm_k4(acc1, wt1, hb1, k4, wv);
                ACT_PAIR(acc2, c2r, h2dst, k4);
            }
            #pragma unroll 1
            for (int k4 = 8; k4 < 32; ++k4)
                gemm_k4(acc1, wt1, hb1, k4, wv);
        }
        __syncthreads();   // bar2: h2(t) visible
    }

    // ---- epilogue: proj(TT-1) + output_cyto from final h2 (buffer 0, TT even) ----
    {
        const float* hf = h2s;
        float a0 = b1s[oo_out];
        float a1 = b2s[oo_out];
        #pragma unroll 8
        for (int k = 0; k < HH; ++k) {
            const float hv = hf[k * HSTR + rr_out];
            a0 = fmaf(hv, W1s[k * NOUT + oo_out], a0);
            a1 = fmaf(hv, W2s[k * NOUT + oo_out], a1);
        }
        out[OUTS_BASE + ((size_t)(r0 + rr_out) * TT + (TT - 1)) * NOUT + oo_out] = a0;
        out[(size_t)(r0 + rr_out) * NOUT + oo_out] = a1;
    }
}

extern "C" void kernel_launch(void* const* d_in, const int* in_sizes, int n_in,
                              void* d_out, int out_size)
{
    (void)n_in; (void)out_size;
    const int o = (n_in >= 2 && in_sizes[1] == 1) ? 2 : 1;

    const float* x    = (const float*)d_in[0];
    const float* wih1 = (const float*)d_in[o + 0];
    const float* whh1 = (const float*)d_in[o + 1];
    const float* bih1 = (const float*)d_in[o + 2];
    const float* bhh1 = (const float*)d_in[o + 3];
    const float* wih2 = (const float*)d_in[o + 4];
    const float* whh2 = (const float*)d_in[o + 5];
    const float* bih2 = (const float*)d_in[o + 6];
    const float* bhh2 = (const float*)d_in[o + 7];
    const float* W1   = (const float*)d_in[o + 8];
    const float* b1   = (const float*)d_in[o + 9];
    const float* W2   = (const float*)d_in[o + 10];
    const float* b2   = (const float*)d_in[o + 11];

    // 1) transpose weights into __device__ scratch (k-major, gates packed)
    prep_w_kernel<<<(HH * HH + 255) / 256, 256>>>(whh1, wih2, whh2);

    // 2) main persistent recurrence kernel (software-pipelined phases)
    const size_t smem = (size_t)SM_TOT * sizeof(float);   // ~104 KB
    cudaFuncSetAttribute(lstm_kernel,
                         cudaFuncAttributeMaxDynamicSharedMemorySize, (int)smem);
    lstm_kernel<<<NCTA, NTHR, smem>>>(x, wih1, bih1, bhh1, bih2, bhh2,
                                      W1, b1, W2, b2, (float*)d_out);
}

// round 9
// speedup vs baseline: 1.3469x; 1.0056x over previous
#include <cuda_runtime.h>
#include <cstdint>

// Problem constants
#define BB   4096
#define TT   2048
#define HH   128
#define BR   32            // batch rows per CTA
#define NCTA (BB / BR)     // 128 CTAs
#define NTHR 256           // 8 warps -> 2 per SMSP
#define NOUT 8
#define HSTR 36            // smem row stride (floats): 144B, 16B-aligned (LDS.128-safe)

typedef unsigned long long ull;

// ---------- packed fp32x2 helpers ----------
__device__ __forceinline__ ull pack2(float a, float b) {
    ull r; asm("mov.b64 %0,{%1,%2};" : "=l"(r) : "f"(a), "f"(b)); return r;
}
__device__ __forceinline__ void unpack2(ull p, float& a, float& b) {
    asm("mov.b64 {%0,%1},%2;" : "=f"(a), "=f"(b) : "l"(p));
}
__device__ __forceinline__ ull fma2(ull a, ull b, ull c) {
    ull d; asm("fma.rn.f32x2 %0,%1,%2,%3;" : "=l"(d) : "l"(a), "l"(b), "l"(c)); return d;
}

// ---------- HW tanh activations (sm_75+ MUFU.TANH; 1 MUFU each) ----------
__device__ __forceinline__ float tanha(float x) {
    float r; asm("tanh.approx.f32 %0,%1;" : "=f"(r) : "f"(x)); return r;
}
__device__ __forceinline__ float sigf(float x) {           // sigmoid via tanh: 1 MUFU + 2 FMA
    return fmaf(0.5f, tanha(0.5f * x), 0.5f);
}

// Transposed weights: [mat][k*128 + j] = float4 (g0,g1,g2,g3) for unit j, col k.
// Lanes j..j+31 are 16B-contiguous -> 4 lines per LDG.128 (coalesced).
__device__ float4 g_wt[3][HH * HH];

__global__ void prep_w_kernel(const float* __restrict__ whh1,
                              const float* __restrict__ wih2,
                              const float* __restrict__ whh2)
{
    const int idx = blockIdx.x * blockDim.x + threadIdx.x;   // 0..16383
    if (idx >= HH * HH) return;
    const int k = idx >> 7, j = idx & 127;
    const float* Ws[3] = { whh1, wih2, whh2 };
    #pragma unroll
    for (int m = 0; m < 3; ++m) {
        const float* W = Ws[m];
        g_wt[m][idx] = make_float4(W[(0 * HH + j) * HH + k],
                                   W[(1 * HH + j) * HH + k],
                                   W[(2 * HH + j) * HH + k],
                                   W[(3 * HH + j) * HH + k]);
    }
}

// One k4-group (4 k values) of the 16x512x128 GEMM slice; weight prefetch carried in wv.
__device__ __forceinline__ void gemm_k4(ull (&acc)[4][8],
                                        const float4* __restrict__ wt,    // g_wt[m] + j
                                        const float* __restrict__ hbuf,   // h + rbase
                                        int k4, float4 (&wv)[4])
{
    float4 wn[4];
    const int kb = (k4 < 31) ? (k4 + 1) * 4 : 124;      // prefetch next 4 k
    #pragma unroll
    for (int i = 0; i < 4; ++i) wn[i] = __ldg(wt + (kb + i) * HH);
    const float* hk = hbuf + (k4 * 4) * HSTR;
    #pragma unroll
    for (int kk = 0; kk < 4; ++kk) {
        const ull wp0 = pack2(wv[kk].x, wv[kk].x);
        const ull wp1 = pack2(wv[kk].y, wv[kk].y);
        const ull wp2 = pack2(wv[kk].z, wv[kk].z);
        const ull wp3 = pack2(wv[kk].w, wv[kk].w);
        const float* hkk = hk + kk * HSTR;
        #pragma unroll
        for (int rq = 0; rq < 4; ++rq) {                 // quad of rows: LDS.128
            const float4 h4 = *(const float4*)(hkk + 4 * rq);
            const ull hp0 = pack2(h4.x, h4.y);
            const ull hp1 = pack2(h4.z, h4.w);
            const int rp = 2 * rq;
            acc[0][rp]   = fma2(wp0, hp0, acc[0][rp]);
            acc[1][rp]   = fma2(wp1, hp0, acc[1][rp]);
            acc[2][rp]   = fma2(wp2, hp0, acc[2][rp]);
            acc[3][rp]   = fma2(wp3, hp0, acc[3][rp]);
            acc[0][rp+1] = fma2(wp0, hp1, acc[0][rp+1]);
            acc[1][rp+1] = fma2(wp1, hp1, acc[1][rp+1]);
            acc[2][rp+1] = fma2(wp2, hp1, acc[2][rp+1]);
            acc[3][rp+1] = fma2(wp3, hp1, acc[3][rp+1]);
        }
    }
    #pragma unroll
    for (int i = 0; i < 4; ++i) wv[i] = wn[i];
}

// One row-pair of activations (gates -> c,h), static pair index P (regs).
#define ACT_PAIR(accX, cX, hdst, P) do {                                     \
    float iv0, iv1, fv0, fv1, gv0, gv1, ov0, ov1;                            \
    unpack2(accX[0][P], iv0, iv1);                                           \
    unpack2(accX[1][P], fv0, fv1);                                           \
    unpack2(accX[2][P], gv0, gv1);                                           \
    unpack2(accX[3][P], ov0, ov1);                                           \
    {   const float cn = sigf(fv0) * cX[2*(P)] + sigf(iv0) * tanha(gv0);     \
        cX[2*(P)] = cn;                                                      \
        (hdst)[2*(P)] = sigf(ov0) * tanha(cn); }                             \
    {   const float cn = sigf(fv1) * cX[2*(P)+1] + sigf(iv1) * tanha(gv1);   \
        cX[2*(P)+1] = cn;                                                    \
        (hdst)[2*(P)+1] = sigf(ov1) * tanha(cn); }                           \
} while (0)

// Dynamic smem layout (floats)
#define SM_H1  0                          // [2][128][HSTR]
#define SM_H2  (SM_H1 + 2 * HH * HSTR)    // [2][128][HSTR]
#define SM_XS  (SM_H2 + 2 * HH * HSTR)    // [64][HSTR]
#define SM_W1  (SM_XS + 64 * HSTR)        // [128][8] transposed [k][oo]
#define SM_W2  (SM_W1 + NOUT * HH)        // [128][8]
#define SM_B1  (SM_W2 + NOUT * HH)        // [8]
#define SM_B2  (SM_B1 + NOUT)             // [8]
#define SM_SB1 (SM_B2 + NOUT)             // [128][8] packed (bb1,bb1) per gate, per j
#define SM_SB2 (SM_SB1 + HH * 8)          // [128][8] packed (bb2,bb2)
#define SM_SWI (SM_SB2 + HH * 8)          // [128][8] packed (wi,wi)
#define SM_TOT (SM_SWI + HH * 8)          // ~103.6 KB

__global__ void __launch_bounds__(NTHR, 1)
lstm_kernel(const float* __restrict__ x,
            const float* __restrict__ wih1,
            const float* __restrict__ bih1, const float* __restrict__ bhh1,
            const float* __restrict__ bih2, const float* __restrict__ bhh2,
            const float* __restrict__ W1, const float* __restrict__ b1,
            const float* __restrict__ W2, const float* __restrict__ b2,
            float* __restrict__ out)
{
    extern __shared__ float sm[];
    float* h1s = sm + SM_H1;
    float* h2s = sm + SM_H2;
    float* xs  = sm + SM_XS;
    float* W1s = sm + SM_W1;
    float* W2s = sm + SM_W2;
    float* b1s = sm + SM_B1;
    float* b2s = sm + SM_B2;
    float* sb1 = sm + SM_SB1;
    float* sb2 = sm + SM_SB2;
    float* swi = sm + SM_SWI;

    const int tid = threadIdx.x;
    const int j   = tid & 127;           // hidden unit owned by this thread
    const int rh  = tid >> 7;            // row half: rows [rh*16, rh*16+16)
    const int r0  = blockIdx.x * BR;     // first batch row of this CTA

    // ---- init smem ----
    for (int i = tid; i < 2 * HH * HSTR; i += NTHR) { h1s[i] = 0.0f; h2s[i] = 0.0f; }
    for (int i = tid; i < NOUT * HH;     i += NTHR) {
        const int oo = i / HH, k = i % HH;
        W1s[k * NOUT + oo] = W1[i];
        W2s[k * NOUT + oo] = W2[i];
    }
    if (tid < NOUT) { b1s[tid] = b1[tid]; b2s[tid] = b2[tid]; }
    if (tid < HH) {
        #pragma unroll
        for (int g = 0; g < 4; ++g) {
            const int row = g * HH + tid;
            const float bb1 = bih1[row] + bhh1[row];
            const float bb2 = bih2[row] + bhh2[row];
            const float wv  = wih1[row];           // W_ih1 is (512,1)
            sb1[tid * 8 + 2 * g] = bb1; sb1[tid * 8 + 2 * g + 1] = bb1;
            sb2[tid * 8 + 2 * g] = bb2; sb2[tid * 8 + 2 * g + 1] = bb2;
            swi[tid * 8 + 2 * g] = wv;  swi[tid * 8 + 2 * g + 1] = wv;
        }
    }
    // ---- stage x tile 0 ----
    for (int idx = tid; idx < BR * 64; idx += NTHR) {
        const int rr = idx >> 6, tt2 = idx & 63;
        xs[tt2 * HSTR + rr] = x[(size_t)(r0 + rr) * TT + tt2];
    }

    // cell state in registers
    float c1r[16], c2r[16];
    #pragma unroll
    for (int i = 0; i < 16; ++i) { c1r[i] = 0.0f; c2r[i] = 0.0f; }

    const float4* wt1 = g_wt[0] + j;   // whh1
    const float4* wt2 = g_wt[1] + j;   // wih2
    const float4* wt3 = g_wt[2] + j;   // whh2
    const ull* b1pj = (const ull*)(sb1 + j * 8);
    const ull* b2pj = (const ull*)(sb2 + j * 8);
    const ull* wipj = (const ull*)(swi + j * 8);

    __syncthreads();

    ull acc1[4][8], acc2[4][8];
    const int rbase  = rh * 16;
    const int rr_out = tid >> 3;
    const int oo_out = tid & 7;
    const size_t OUTS_BASE = (size_t)BB * NOUT;

    // ---- prologue: acc1 = preacts(step 0) = b1 + wi*x(0)  (h1(-1)=0) ----
    {
        const float* xrow = xs + rbase;
        #pragma unroll
        for (int rq = 0; rq < 4; ++rq) {
            const ulonglong2 xv = *(const ulonglong2*)(xrow + 4 * rq);
            const int rp = 2 * rq;
            #pragma unroll
            for (int g = 0; g < 4; ++g) {
                acc1[g][rp]   = fma2(wipj[g], xv.x, b1pj[g]);
                acc1[g][rp+1] = fma2(wipj[g], xv.y, b1pj[g]);
            }
        }
    }

    #pragma unroll 1
    for (int t = 0; t < TT; ++t) {
        const int cur = t & 1, nxt = cur ^ 1;
        float* h1n = h1s + nxt * (HH * HSTR);
        float* h2c = h2s + cur * (HH * HSTR);
        float* h2n = h2s + nxt * (HH * HSTR);
        const float* hb1 = h1n + rbase;
        const float* hb2 = h2c + rbase;

        // ======== P1: gemm whh2*h2(t-1) into acc2, fused with act1 + proj(t-1) ========
        #pragma unroll
        for (int rp = 0; rp < 8; ++rp) {
            acc2[0][rp] = b2pj[0]; acc2[1][rp] = b2pj[1];
            acc2[2][rp] = b2pj[2]; acc2[3][rp] = b2pj[3];
        }
        {
            float4 wv[4];
            #pragma unroll
            for (int i = 0; i < 4; ++i) wv[i] = __ldg(wt3 + i * HH);
            float* h1dst = h1n + j * HSTR + rbase;
            #pragma unroll
            for (int k4 = 0; k4 < 8; ++k4) {        // fused: one act pair per group
                gemm_k4(acc2, wt3, hb2, k4, wv);
                ACT_PAIR(acc1, c1r, h1dst, k4);
            }
            float a0 = b1s[oo_out];
            #pragma unroll 1
            for (int k4 = 8; k4 < 32; ++k4) {       // fused: proj chunks of 8 k
                gemm_k4(acc2, wt3, hb2, k4, wv);
                if (k4 < 24) {
                    const int kk0 = (k4 - 8) * 8;
                    #pragma unroll
                    for (int q = 0; q < 8; ++q)
                        a0 = fmaf(h2c[(kk0 + q) * HSTR + rr_out],
                                  W1s[(kk0 + q) * NOUT + oo_out], a0);
                }
            }
            if (t)
                out[OUTS_BASE + ((size_t)(r0 + rr_out) * TT + (t - 1)) * NOUT + oo_out] = a0;
        }
        __syncthreads();   // bar1: h1(t) visible

        // ======== P2: gemm wih2*h1(t) into acc2 ========
        {
            float4 wv[4];
            #pragma unroll
            for (int i = 0; i < 4; ++i) wv[i] = __ldg(wt2 + i * HH);
            #pragma unroll 1
            for (int k4 = 0; k4 < 32; ++k4)
                gemm_k4(acc2, wt2, hb1, k4, wv);
        }

        // ---- stage next x tile when needed (P3 reads x(t+1)) ----
        if (((t + 1) & 63) == 0 && (t + 1) < TT) {
            for (int idx = tid; idx < BR * 64; idx += NTHR) {
                const int rr = idx >> 6, tt2 = idx & 63;
                xs[tt2 * HSTR + rr] = x[(size_t)(r0 + rr) * TT + (t + 1) + tt2];
            }
            __syncthreads();
        }

        // ======== P3: gemm whh1*h1(t) (+x(t+1)) into acc1, fused with act2 ========
        {
            const float* xrow = xs + ((t + 1) & 63) * HSTR + rbase;
            #pragma unroll
            for (int rq = 0; rq < 4; ++rq) {
                const ulonglong2 xv = *(const ulonglong2*)(xrow + 4 * rq);
                const int rp = 2 * rq;
                #pragma unroll
                for (int g = 0; g < 4; ++g) {
                    acc1[g][rp]   = fma2(wipj[g], xv.x, b1pj[g]);
                    acc1[g][rp+1] = fma2(wipj[g], xv.y, b1pj[g]);
                }
            }
            float4 wv[4];
            #pragma unroll
            for (int i = 0; i < 4; ++i) wv[i] = __ldg(wt1 + i * HH);
            float* h2dst = h2n + j * HSTR + rbase;
            #pragma unroll
            for (int k4 = 0; k4 < 8; ++k4) {        // fused: one act pair per group
                gemm_k4(acc1, wt1, hb1, k4, wv);
                ACT_PAIR(acc2, c2r, h2dst, k4);
            }
            #pragma unroll 1
            for (int k4 = 8; k4 < 32; ++k4)
                gemm_k4(acc1, wt1, hb1, k4, wv);
        }
        __syncthreads();   // bar2: h2(t) visible
    }

    // ---- epilogue: proj(TT-1) + output_cyto from final h2 (buffer 0, TT even) ----
    {
        const float* hf = h2s;
        float a0 = b1s[oo_out];
        float a1 = b2s[oo_out];
        #pragma unroll 8
        for (int k = 0; k < HH; ++k) {
            const float hv = hf[k * HSTR + rr_out];
            a0 = fmaf(hv, W1s[k * NOUT + oo_out], a0);
            a1 = fmaf(hv, W2s[k * NOUT + oo_out], a1);
        }
        out[OUTS_BASE + ((size_t)(r0 + rr_out) * TT + (TT - 1)) * NOUT + oo_out] = a0;
        out[(size_t)(r0 + rr_out) * NOUT + oo_out] = a1;
    }
}

extern "C" void kernel_launch(void* const* d_in, const int* in_sizes, int n_in,
                              void* d_out, int out_size)
{
    (void)n_in; (void)out_size;
    const int o = (n_in >= 2 && in_sizes[1] == 1) ? 2 : 1;

    const float* x    = (const float*)d_in[0];
    const float* wih1 = (const float*)d_in[o + 0];
    const float* whh1 = (const float*)d_in[o + 1];
    const float* bih1 = (const float*)d_in[o + 2];
    const float* bhh1 = (const float*)d_in[o + 3];
    const float* wih2 = (const float*)d_in[o + 4];
    const float* whh2 = (const float*)d_in[o + 5];
    const float* bih2 = (const float*)d_in[o + 6];
    const float* bhh2 = (const float*)d_in[o + 7];
    const float* W1   = (const float*)d_in[o + 8];
    const float* b1   = (const float*)d_in[o + 9];
    const float* W2   = (const float*)d_in[o + 10];
    const float* b2   = (const float*)d_in[o + 11];

    // 1) transpose weights into __device__ scratch (k-major, gates packed)
    prep_w_kernel<<<(HH * HH + 255) / 256, 256>>>(whh1, wih2, whh2);

    // 2) main persistent recurrence kernel (software-pipelined phases)
    const size_t smem = (size_t)SM_TOT * sizeof(float);   // ~104 KB
    cudaFuncSetAttribute(lstm_kernel,
                         cudaFuncAttributeMaxDynamicSharedMemorySize, (int)smem);
    lstm_kernel<<<NCTA, NTHR, smem>>>(x, wih1, bih1, bhh1, bih2, bhh2,
                                      W1, b1, W2, b2, (float*)d_out);
}

// round 10
// speedup vs baseline: 1.4330x; 1.0640x over previous
#include <cuda_runtime.h>
#include <cstdint>

// Problem constants
#define BB   4096
#define TT   2048
#define HH   128
#define BR   28            // batch rows per CTA (148 x 28 = 4144 >= 4096, tail padded)
#define NCTA 148           // one CTA per SM — no idle SMs
#define NTHR 256           // 8 warps -> 2 per SMSP
#define NOUT 8
#define HSTR 36            // smem row stride (floats): 144B, 16B-aligned (LDS.128-safe)

typedef unsigned long long ull;

// Non-aligned barrier: all 256 threads arrive (possibly via divergent template paths)
#define BARSYNC() asm volatile("barrier.sync 0;" ::: "memory")

// ---------- packed fp32x2 helpers ----------
__device__ __forceinline__ ull pack2(float a, float b) {
    ull r; asm("mov.b64 %0,{%1,%2};" : "=l"(r) : "f"(a), "f"(b)); return r;
}
__device__ __forceinline__ void unpack2(ull p, float& a, float& b) {
    asm("mov.b64 {%0,%1},%2;" : "=f"(a), "=f"(b) : "l"(p));
}
__device__ __forceinline__ ull fma2(ull a, ull b, ull c) {
    ull d; asm("fma.rn.f32x2 %0,%1,%2,%3;" : "=l"(d) : "l"(a), "l"(b), "l"(c)); return d;
}

// ---------- HW tanh activations (MUFU.TANH) ----------
__device__ __forceinline__ float tanha(float x) {
    float r; asm("tanh.approx.f32 %0,%1;" : "=f"(r) : "f"(x)); return r;
}
__device__ __forceinline__ float sigf(float x) {
    return fmaf(0.5f, tanha(0.5f * x), 0.5f);
}

// Transposed weights: [mat][k*128 + j] = float4 (g0,g1,g2,g3) for unit j, col k.
__device__ float4 g_wt[3][HH * HH];

__global__ void prep_w_kernel(const float* __restrict__ whh1,
                              const float* __restrict__ wih2,
                              const float* __restrict__ whh2)
{
    const int idx = blockIdx.x * blockDim.x + threadIdx.x;
    if (idx >= HH * HH) return;
    const int k = idx >> 7, j = idx & 127;
    const float* Ws[3] = { whh1, wih2, whh2 };
    #pragma unroll
    for (int m = 0; m < 3; ++m) {
        const float* W = Ws[m];
        g_wt[m][idx] = make_float4(W[(0 * HH + j) * HH + k],
                                   W[(1 * HH + j) * HH + k],
                                   W[(2 * HH + j) * HH + k],
                                   W[(3 * HH + j) * HH + k]);
    }
}

// One k4-group of the GEMM slice; NRQ = number of row quads this thread owns (4 or 3).
template<int NRQ>
__device__ __forceinline__ void gemm_k4(ull (&acc)[4][8],
                                        const float4* __restrict__ wt,
                                        const float* __restrict__ hbuf,   // h + rbase
                                        int k4, float4 (&wv)[4])
{
    float4 wn[4];
    const int kb = (k4 < 31) ? (k4 + 1) * 4 : 124;
    #pragma unroll
    for (int i = 0; i < 4; ++i) wn[i] = __ldg(wt + (kb + i) * HH);
    const float* hk = hbuf + (k4 * 4) * HSTR;
    #pragma unroll
    for (int kk = 0; kk < 4; ++kk) {
        const ull wp0 = pack2(wv[kk].x, wv[kk].x);
        const ull wp1 = pack2(wv[kk].y, wv[kk].y);
        const ull wp2 = pack2(wv[kk].z, wv[kk].z);
        const ull wp3 = pack2(wv[kk].w, wv[kk].w);
        const float* hkk = hk + kk * HSTR;
        #pragma unroll
        for (int rq = 0; rq < NRQ; ++rq) {
            const float4 h4 = *(const float4*)(hkk + 4 * rq);
            const ull hp0 = pack2(h4.x, h4.y);
            const ull hp1 = pack2(h4.z, h4.w);
            const int rp = 2 * rq;
            acc[0][rp]   = fma2(wp0, hp0, acc[0][rp]);
            acc[1][rp]   = fma2(wp1, hp0, acc[1][rp]);
            acc[2][rp]   = fma2(wp2, hp0, acc[2][rp]);
            acc[3][rp]   = fma2(wp3, hp0, acc[3][rp]);
            acc[0][rp+1] = fma2(wp0, hp1, acc[0][rp+1]);
            acc[1][rp+1] = fma2(wp1, hp1, acc[1][rp+1]);
            acc[2][rp+1] = fma2(wp2, hp1, acc[2][rp+1]);
            acc[3][rp+1] = fma2(wp3, hp1, acc[3][rp+1]);
        }
    }
    #pragma unroll
    for (int i = 0; i < 4; ++i) wv[i] = wn[i];
}

// One row-pair of activations (gates -> c,h), static pair index P.
#define ACT_PAIR(accX, cX, hdst, P) do {                                     \
    float iv0, iv1, fv0, fv1, gv0, gv1, ov0, ov1;                            \
    unpack2(accX[0][P], iv0, iv1);                                           \
    unpack2(accX[1][P], fv0, fv1);                                           \
    unpack2(accX[2][P], gv0, gv1);                                           \
    unpack2(accX[3][P], ov0, ov1);                                           \
    {   const float cn = sigf(fv0) * cX[2*(P)] + sigf(iv0) * tanha(gv0);     \
        cX[2*(P)] = cn;                                                      \
        (hdst)[2*(P)] = sigf(ov0) * tanha(cn); }                             \
    {   const float cn = sigf(fv1) * cX[2*(P)+1] + sigf(iv1) * tanha(gv1);   \
        cX[2*(P)+1] = cn;                                                    \
        (hdst)[2*(P)+1] = sigf(ov1) * tanha(cn); }                           \
} while (0)

// Dynamic smem layout (floats)
#define SM_H1  0                          // [2][128][HSTR]
#define SM_H2  (SM_H1 + 2 * HH * HSTR)    // [2][128][HSTR]
#define SM_XS  (SM_H2 + 2 * HH * HSTR)    // [64][HSTR]
#define SM_W1  (SM_XS + 64 * HSTR)        // [128][8] transposed [k][oo]
#define SM_W2  (SM_W1 + NOUT * HH)        // [128][8]
#define SM_B1  (SM_W2 + NOUT * HH)        // [8]
#define SM_B2  (SM_B1 + NOUT)             // [8]
#define SM_SB1 (SM_B2 + NOUT)             // [128][8] packed (bb1,bb1) per gate, per j
#define SM_SB2 (SM_SB1 + HH * 8)          // [128][8] packed (bb2,bb2)
#define SM_SWI (SM_SB2 + HH * 8)          // [128][8] packed (wi,wi)
#define SM_TOT (SM_SWI + HH * 8)          // ~103.6 KB

// The full recurrence loop, templated on this warp-group's quad count.
// rh=0 warps: NRQ=4 (rows 0..15); rh=1 warps: NRQ=3 (rows 16..27).
// All barriers are non-aligned barrier.sync 0 — every thread of the block
// arrives each time (counts match across both instantiations).
template<int NRQ>
__device__ __forceinline__ void run_steps(
    float* __restrict__ h1s, float* __restrict__ h2s, float* __restrict__ xs,
    const float* __restrict__ W1s, const float* __restrict__ b1s,
    const ull* __restrict__ b1pj, const ull* __restrict__ b2pj,
    const ull* __restrict__ wipj,
    const float4* __restrict__ wt1, const float4* __restrict__ wt2,
    const float4* __restrict__ wt3,
    const float* __restrict__ x, float* __restrict__ out,
    int j, int rbase, int r0, int rr_out, int oo_out, int tid)
{
    float c1r[2 * NRQ * 2], c2r[2 * NRQ * 2];
    #pragma unroll
    for (int i = 0; i < 4 * NRQ; ++i) { c1r[i] = 0.0f; c2r[i] = 0.0f; }

    ull acc1[4][8], acc2[4][8];
    const bool wout = (rr_out < BR) && (r0 + rr_out < BB);
    const size_t OUTS_BASE = (size_t)BB * NOUT;

    // ---- prologue: acc1 = b1 + wi*x(0)  (h1(-1)=0) ----
    {
        const float* xrow = xs + rbase;
        #pragma unroll
        for (int rq = 0; rq < NRQ; ++rq) {
            const ulonglong2 xv = *(const ulonglong2*)(xrow + 4 * rq);
            const int rp = 2 * rq;
            #pragma unroll
            for (int g = 0; g < 4; ++g) {
                acc1[g][rp]   = fma2(wipj[g], xv.x, b1pj[g]);
                acc1[g][rp+1] = fma2(wipj[g], xv.y, b1pj[g]);
            }
        }
    }

    #pragma unroll 1
    for (int t = 0; t < TT; ++t) {
        const int cur = t & 1, nxt = cur ^ 1;
        float* h1n = h1s + nxt * (HH * HSTR);
        float* h2c = h2s + cur * (HH * HSTR);
        float* h2n = h2s + nxt * (HH * HSTR);
        const float* hb1 = h1n + rbase;
        const float* hb2 = h2c + rbase;

        // ==== P1: gemm whh2*h2(t-1) -> acc2, fused with act1 + proj(t-1) ====
        #pragma unroll
        for (int rp = 0; rp < 2 * NRQ; ++rp) {
            acc2[0][rp] = b2pj[0]; acc2[1][rp] = b2pj[1];
            acc2[2][rp] = b2pj[2]; acc2[3][rp] = b2pj[3];
        }
        {
            float4 wv[4];
            #pragma unroll
            for (int i = 0; i < 4; ++i) wv[i] = __ldg(wt3 + i * HH);
            float* h1dst = h1n + j * HSTR + rbase;
            #pragma unroll
            for (int k4 = 0; k4 < 8; ++k4) {
                gemm_k4<NRQ>(acc2, wt3, hb2, k4, wv);
                if (k4 < 2 * NRQ) ACT_PAIR(acc1, c1r, h1dst, k4);
            }
            float a0 = b1s[oo_out];
            #pragma unroll 1
            for (int k4 = 8; k4 < 32; ++k4) {
                gemm_k4<NRQ>(acc2, wt3, hb2, k4, wv);
                if (k4 < 24) {
                    const int kk0 = (k4 - 8) * 8;
                    #pragma unroll
                    for (int q = 0; q < 8; ++q)
                        a0 = fmaf(h2c[(kk0 + q) * HSTR + rr_out],
                                  W1s[(kk0 + q) * NOUT + oo_out], a0);
                }
            }
            if (t && wout)
                out[OUTS_BASE + ((size_t)(r0 + rr_out) * TT + (t - 1)) * NOUT + oo_out] = a0;
        }
        BARSYNC();   // bar1: h1(t) visible

        // ==== P2: gemm wih2*h1(t) -> acc2 ====
        {
            float4 wv[4];
            #pragma unroll
            for (int i = 0; i < 4; ++i) wv[i] = __ldg(wt2 + i * HH);
            #pragma unroll 1
            for (int k4 = 0; k4 < 32; ++k4)
                gemm_k4<NRQ>(acc2, wt2, hb1, k4, wv);
        }

        // ---- stage next x tile (uniform condition across the block) ----
        if (((t + 1) & 63) == 0 && (t + 1) < TT) {
            for (int idx = tid; idx < BR * 64; idx += NTHR) {
                const int rr = idx >> 6, tt2 = idx & 63;
                const int gr = r0 + rr;
                xs[tt2 * HSTR + rr] =
                    x[(size_t)(gr < BB ? gr : BB - 1) * TT + (t + 1) + tt2];
            }
            BARSYNC();
        }

        // ==== P3: gemm whh1*h1(t) (+x(t+1)) -> acc1, fused with act2 ====
        {
            const float* xrow = xs + ((t + 1) & 63) * HSTR + rbase;
            #pragma unroll
            for (int rq = 0; rq < NRQ; ++rq) {
                const ulonglong2 xv = *(const ulonglong2*)(xrow + 4 * rq);
                const int rp = 2 * rq;
                #pragma unroll
                for (int g = 0; g < 4; ++g) {
                    acc1[g][rp]   = fma2(wipj[g], xv.x, b1pj[g]);
                    acc1[g][rp+1] = fma2(wipj[g], xv.y, b1pj[g]);
                }
            }
            float4 wv[4];
            #pragma unroll
            for (int i = 0; i < 4; ++i) wv[i] = __ldg(wt1 + i * HH);
            float* h2dst = h2n + j * HSTR + rbase;
            #pragma unroll
            for (int k4 = 0; k4 < 8; ++k4) {
                gemm_k4<NRQ>(acc1, wt1, hb1, k4, wv);
                if (k4 < 2 * NRQ) ACT_PAIR(acc2, c2r, h2dst, k4);
            }
            #pragma unroll 1
            for (int k4 = 8; k4 < 32; ++k4)
                gemm_k4<NRQ>(acc1, wt1, hb1, k4, wv);
        }
        BARSYNC();   // bar2: h2(t) visible
    }
}

__global__ void __launch_bounds__(NTHR, 1)
lstm_kernel(const float* __restrict__ x,
            const float* __restrict__ wih1,
            const float* __restrict__ bih1, const float* __restrict__ bhh1,
            const float* __restrict__ bih2, const float* __restrict__ bhh2,
            const float* __restrict__ W1, const float* __restrict__ b1,
            const float* __restrict__ W2, const float* __restrict__ b2,
            float* __restrict__ out)
{
    extern __shared__ float sm[];
    float* h1s = sm + SM_H1;
    float* h2s = sm + SM_H2;
    float* xs  = sm + SM_XS;
    float* W1s = sm + SM_W1;
    float* W2s = sm + SM_W2;
    float* b1s = sm + SM_B1;
    float* b2s = sm + SM_B2;
    float* sb1 = sm + SM_SB1;
    float* sb2 = sm + SM_SB2;
    float* swi = sm + SM_SWI;

    const int tid = threadIdx.x;
    const int j   = tid & 127;           // hidden unit owned by this thread
    const int rh  = tid >> 7;            // 0: rows 0..15 (4 quads); 1: rows 16..27 (3)
    const int r0  = blockIdx.x * BR;     // first batch row of this CTA

    // ---- init smem ----
    for (int i = tid; i < 2 * HH * HSTR; i += NTHR) { h1s[i] = 0.0f; h2s[i] = 0.0f; }
    for (int i = tid; i < NOUT * HH;     i += NTHR) {
        const int oo = i / HH, k = i % HH;
        W1s[k * NOUT + oo] = W1[i];
        W2s[k * NOUT + oo] = W2[i];
    }
    if (tid < NOUT) { b1s[tid] = b1[tid]; b2s[tid] = b2[tid]; }
    if (tid < HH) {
        #pragma unroll
        for (int g = 0; g < 4; ++g) {
            const int row = g * HH + tid;
            const float bb1 = bih1[row] + bhh1[row];
            const float bb2 = bih2[row] + bhh2[row];
            const float wv  = wih1[row];           // W_ih1 is (512,1)
            sb1[tid * 8 + 2 * g] = bb1; sb1[tid * 8 + 2 * g + 1] = bb1;
            sb2[tid * 8 + 2 * g] = bb2; sb2[tid * 8 + 2 * g + 1] = bb2;
            swi[tid * 8 + 2 * g] = wv;  swi[tid * 8 + 2 * g + 1] = wv;
        }
    }
    // ---- stage x tile 0 (clamped rows for the padded tail CTA) ----
    for (int idx = tid; idx < BR * 64; idx += NTHR) {
        const int rr = idx >> 6, tt2 = idx & 63;
        const int gr = r0 + rr;
        xs[tt2 * HSTR + rr] = x[(size_t)(gr < BB ? gr : BB - 1) * TT + tt2];
    }

    const float4* wt1 = g_wt[0] + j;   // whh1
    const float4* wt2 = g_wt[1] + j;   // wih2
    const float4* wt3 = g_wt[2] + j;   // whh2
    const ull* b1pj = (const ull*)(sb1 + j * 8);
    const ull* b2pj = (const ull*)(sb2 + j * 8);
    const ull* wipj = (const ull*)(swi + j * 8);

    const int rr_out = tid >> 3;
    const int oo_out = tid & 7;

    BARSYNC();

    if (rh == 0)
        run_steps<4>(h1s, h2s, xs, W1s, b1s, b1pj, b2pj, wipj,
                     wt1, wt2, wt3, x, out, j, 0,  r0, rr_out, oo_out, tid);
    else
        run_steps<3>(h1s, h2s, xs, W1s, b1s, b1pj, b2pj, wipj,
                     wt1, wt2, wt3, x, out, j, 16, r0, rr_out, oo_out, tid);

    // ---- epilogue: proj(TT-1) + output_cyto from final h2 (buffer 0, TT even) ----
    if ((rr_out < BR) && (r0 + rr_out < BB)) {
        const float* hf = h2s;
        float a0 = b1s[oo_out];
        float a1 = b2s[oo_out];
        #pragma unroll 8
        for (int k = 0; k < HH; ++k) {
            const float hv = hf[k * HSTR + rr_out];
            a0 = fmaf(hv, W1s[k * NOUT + oo_out], a0);
            a1 = fmaf(hv, W2s[k * NOUT + oo_out], a1);
        }
        out[(size_t)BB * NOUT + ((size_t)(r0 + rr_out) * TT + (TT - 1)) * NOUT + oo_out] = a0;
        out[(size_t)(r0 + rr_out) * NOUT + oo_out] = a1;
    }
}

extern "C" void kernel_launch(void* const* d_in, const int* in_sizes, int n_in,
                              void* d_out, int out_size)
{
    (void)n_in; (void)out_size;
    const int o = (n_in >= 2 && in_sizes[1] == 1) ? 2 : 1;

    const float* x    = (const float*)d_in[0];
    const float* wih1 = (const float*)d_in[o + 0];
    const float* whh1 = (const float*)d_in[o + 1];
    const float* bih1 = (const float*)d_in[o + 2];
    const float* bhh1 = (const float*)d_in[o + 3];
    const float* wih2 = (const float*)d_in[o + 4];
    const float* whh2 = (const float*)d_in[o + 5];
    const float* bih2 = (const float*)d_in[o + 6];
    const float* bhh2 = (const float*)d_in[o + 7];
    const float* W1   = (const float*)d_in[o + 8];
    const float* b1   = (const float*)d_in[o + 9];
    const float* W2   = (const float*)d_in[o + 10];
    const float* b2   = (const float*)d_in[o + 11];

    // 1) transpose weights into __device__ scratch (k-major, gates packed)
    prep_w_kernel<<<(HH * HH + 255) / 256, 256>>>(whh1, wih2, whh2);

    // 2) main persistent recurrence kernel (software-pipelined phases, 148 CTAs)
    const size_t smem = (size_t)SM_TOT * sizeof(float);   // ~104 KB
    cudaFuncSetAttribute(lstm_kernel,
                         cudaFuncAttributeMaxDynamicSharedMemorySize, (int)smem);
    lstm_kernel<<<NCTA, NTHR, smem>>>(x, wih1, bih1, bhh1, bih2, bhh2,
                                      W1, b1, W2, b2, (float*)d_out);
}